// round 1
// baseline (speedup 1.0000x reference)
#include <cuda_runtime.h>
#include <math.h>

#define NN 100000
#define NE 600000
#define NG 512
#define HD 128
#define EF 256
#define NCONV 3

// ---- scratch (device globals: allocation-free) ----
__device__ float g_x[NN * HD];     // node features
__device__ float g_A[NN * EF];     // x @ We1
__device__ float g_G[NN * HD];     // x @ Wg
__device__ float g_M[NN * HD];     // per-node message
__device__ float g_agg[NN * HD];   // scatter accumulator
__device__ float g_y[NG * HD];     // graph pooled

__device__ __forceinline__ float sp_(float x) {
    // softplus = logaddexp(x, 0) (matches jax.nn.softplus, stable)
    return fmaxf(x, 0.f) + log1pf(expf(-fabsf(x)));
}
__device__ __forceinline__ float sigm_(float x) {
    return 1.f / (1.f + expf(-x));
}

// ---- zero agg + y ----
__global__ void k_zero() {
    int i = blockIdx.x * blockDim.x + threadIdx.x;
    const int n4 = NN * HD / 4;
    if (i < n4) ((float4*)g_agg)[i] = make_float4(0.f, 0.f, 0.f, 0.f);
    if (i < NG * HD / 4) ((float4*)g_y)[i] = make_float4(0.f, 0.f, 0.f, 0.f);
}

// ---- embedding gather: x[i] = embed[nodes[i]] ----
__global__ void k_embed(const int* __restrict__ nodes, const float* __restrict__ embed) {
    int i = blockIdx.x * blockDim.x + threadIdx.x;  // over NN * 32 float4s
    if (i >= NN * (HD / 4)) return;
    int node = nodes[i / (HD / 4)];
    ((float4*)g_x)[i] = ((const float4*)embed)[node * (HD / 4) + (i & (HD / 4 - 1))];
}

// ---- generic tiled SGEMM: C[M,N] = act_in(A[M,K]) @ W[K,N] + epilogue ----
// ACT_IN: 0 = identity, 1 = softplus on A elements
// EPI:    0 = store, 1 = C = sigmoid(Gb) * softplus(acc), 2 = atomicAdd into C[gidx[row]]
template <int ACT_IN, int EPI>
__global__ void k_gemm(const float* __restrict__ A, const float* __restrict__ W,
                       float* __restrict__ C, const float* __restrict__ Gb,
                       const int* __restrict__ gidx, int M, int N, int K) {
    const int BM = 64, BN = 64, BK = 16;
    __shared__ __align__(16) float As[BK][BM + 4];  // pad
    __shared__ __align__(16) float Ws[BK][BN + 4];

    int tid = threadIdx.x;             // 256 threads
    int m0 = blockIdx.y * BM;
    int n0 = blockIdx.x * BN;
    int tx = tid & 15, ty = tid >> 4;

    float acc[4][4];
#pragma unroll
    for (int i = 0; i < 4; i++)
#pragma unroll
        for (int j = 0; j < 4; j++) acc[i][j] = 0.f;

    for (int k0 = 0; k0 < K; k0 += BK) {
        // load A tile (64 rows x 16 cols)
#pragma unroll
        for (int it = 0; it < 4; it++) {
            int e = tid + it * 256;
            int m = e / BK, k = e % BK;
            int row = m0 + m;
            float v = 0.f;
            if (row < M) v = A[(long)row * K + k0 + k];
            if (ACT_IN == 1) v = sp_(v);
            As[k][m] = v;
        }
        // load W tile (16 rows x 64 cols)
#pragma unroll
        for (int it = 0; it < 4; it++) {
            int e = tid + it * 256;
            int k = e / BN, n = e % BN;
            Ws[k][n] = W[(k0 + k) * N + n0 + n];
        }
        __syncthreads();
#pragma unroll
        for (int k = 0; k < BK; k++) {
            float4 a4 = *reinterpret_cast<const float4*>(&As[k][ty * 4]);
            float4 b4 = *reinterpret_cast<const float4*>(&Ws[k][tx * 4]);
            float a[4] = {a4.x, a4.y, a4.z, a4.w};
            float b[4] = {b4.x, b4.y, b4.z, b4.w};
#pragma unroll
            for (int i = 0; i < 4; i++)
#pragma unroll
                for (int j = 0; j < 4; j++) acc[i][j] += a[i] * b[j];
        }
        __syncthreads();
    }

#pragma unroll
    for (int i = 0; i < 4; i++) {
        int row = m0 + ty * 4 + i;
        if (row >= M) continue;
        int seg = (EPI == 2) ? gidx[row] : 0;
#pragma unroll
        for (int j = 0; j < 4; j++) {
            int col = n0 + tx * 4 + j;
            float v = acc[i][j];
            if (EPI == 0) {
                C[(long)row * N + col] = v;
            } else if (EPI == 1) {
                float g = Gb[(long)row * N + col];
                C[(long)row * N + col] = sigm_(g) * sp_(v);
            } else {
                atomicAdd(&C[seg * N + col], v);
            }
        }
    }
}

// ---- edge scatter: agg[tgt] += M[src] ----
__global__ void k_scatter(const int* __restrict__ src, const int* __restrict__ tgt) {
    long i = (long)blockIdx.x * blockDim.x + threadIdx.x;
    if (i >= (long)NE * (HD / 4)) return;
    int e = (int)(i >> 5);   // HD/4 = 32 chunks per edge
    int c = (int)(i & 31);
    int s = src[e], t = tgt[e];
    float4 v = ((const float4*)g_M)[(long)s * 32 + c];
    float* p = &g_agg[(long)t * HD + c * 4];
    atomicAdd(p + 0, v.x);
    atomicAdd(p + 1, v.y);
    atomicAdd(p + 2, v.z);
    atomicAdd(p + 3, v.w);
}

// ---- node update: x += sp(agg); agg = 0 ----
__global__ void k_update() {
    int i = blockIdx.x * blockDim.x + threadIdx.x;
    if (i >= NN * (HD / 4)) return;
    float4 a = ((float4*)g_agg)[i];
    float4 x = ((float4*)g_x)[i];
    x.x += sp_(a.x);
    x.y += sp_(a.y);
    x.z += sp_(a.z);
    x.w += sp_(a.w);
    ((float4*)g_x)[i] = x;
    ((float4*)g_agg)[i] = make_float4(0.f, 0.f, 0.f, 0.f);
}

// ---- per-graph MLP head: out[g] = (sp(sp(sp(y/c) @ W1 + b1) @ W2 + b2)) @ Wr + br ----
__global__ void k_mlp(const float* __restrict__ counts,
                      const float* __restrict__ Wfc1, const float* __restrict__ bfc1,
                      const float* __restrict__ Wfc2, const float* __restrict__ bfc2,
                      const float* __restrict__ Wr, const float* __restrict__ br,
                      float* __restrict__ out) {
    __shared__ float s0[HD];
    __shared__ float s1[HD];
    __shared__ float red[HD];
    int g = blockIdx.x, t = threadIdx.x;

    float yv = g_y[g * HD + t] / counts[g];
    s0[t] = sp_(yv);
    __syncthreads();

    float acc = bfc1[t];
#pragma unroll 8
    for (int k = 0; k < HD; k++) acc += s0[k] * Wfc1[k * HD + t];
    s1[t] = sp_(acc);
    __syncthreads();

    acc = bfc2[t];
#pragma unroll 8
    for (int k = 0; k < HD; k++) acc += s1[k] * Wfc2[k * HD + t];
    float h2 = sp_(acc);

    red[t] = h2 * Wr[t];
    __syncthreads();
    for (int s = HD / 2; s > 0; s >>= 1) {
        if (t < s) red[t] += red[t + s];
        __syncthreads();
    }
    if (t == 0) out[g] = red[0] + br[0];
}

extern "C" void kernel_launch(void* const* d_in, const int* in_sizes, int n_in,
                              void* d_out, int out_size) {
    const int* nodes = (const int*)d_in[0];
    const int* esrc = (const int*)d_in[1];
    const int* etgt = (const int*)d_in[2];
    const int* gidx = (const int*)d_in[3];
    const float* counts = (const float*)d_in[4];
    const float* embed = (const float*)d_in[5];
    const float* Wg = (const float*)d_in[6];
    const float* We1 = (const float*)d_in[7];
    const float* We2 = (const float*)d_in[8];
    const float* Wp = (const float*)d_in[9];
    const float* Wfc1 = (const float*)d_in[10];
    const float* bfc1 = (const float*)d_in[11];
    const float* Wfc2 = (const float*)d_in[12];
    const float* bfc2 = (const float*)d_in[13];
    const float* Wr = (const float*)d_in[14];
    const float* br = (const float*)d_in[15];
    float* out = (float*)d_out;

    float *px, *pA, *pG, *pM, *py;
    cudaGetSymbolAddress((void**)&px, g_x);
    cudaGetSymbolAddress((void**)&pA, g_A);
    cudaGetSymbolAddress((void**)&pG, g_G);
    cudaGetSymbolAddress((void**)&pM, g_M);
    cudaGetSymbolAddress((void**)&py, g_y);

    const int blocksM = (NN + 63) / 64;

    // zero agg + y
    {
        int n = NN * HD / 4;
        k_zero<<<(n + 255) / 256, 256>>>();
    }
    // embed
    {
        int n = NN * (HD / 4);
        k_embed<<<(n + 255) / 256, 256>>>(nodes, embed);
    }
    // 3 gated convs
    for (int i = 0; i < NCONV; i++) {
        // A = x @ We1[i]   [NN, EF]
        k_gemm<0, 0><<<dim3(EF / 64, blocksM), 256>>>(
            px, We1 + (long)i * HD * EF, pA, nullptr, nullptr, NN, EF, HD);
        // G = x @ Wg[i]    [NN, HD]
        k_gemm<0, 0><<<dim3(HD / 64, blocksM), 256>>>(
            px, Wg + (long)i * HD * HD, pG, nullptr, nullptr, NN, HD, HD);
        // M = sigmoid(G) * sp( sp(A) @ We2[i] )
        k_gemm<1, 1><<<dim3(HD / 64, blocksM), 256>>>(
            pA, We2 + (long)i * EF * HD, pM, pG, nullptr, NN, HD, EF);
        // scatter-add over edges
        {
            long n = (long)NE * (HD / 4);
            k_scatter<<<(int)((n + 255) / 256), 256>>>(esrc, etgt);
        }
        // x += sp(agg); agg = 0
        {
            int n = NN * (HD / 4);
            k_update<<<(n + 255) / 256, 256>>>();
        }
    }
    // pooling: y[g] += (x @ Wp)[i] for graph_indices[i] == g  (fused segment atomics)
    k_gemm<0, 2><<<dim3(HD / 64, blocksM), 256>>>(
        px, Wp, py, nullptr, gidx, NN, HD, HD);
    // head MLP
    k_mlp<<<NG, HD>>>(counts, Wfc1, bfc1, Wfc2, bfc2, Wr, br, out);
}

// round 3
// speedup vs baseline: 1.3908x; 1.3908x over previous
#include <cuda_runtime.h>
#include <cuda_bf16.h>
#include <cstdint>
#include <math.h>

#define NN 100000
#define NE 600000
#define NG 512
#define HD 128
#define EF 256
#define NCONV 3

// ---- scratch (device globals: allocation-free) ----
__device__ float g_x[NN * HD];
__device__ float g_A[NN * EF];
__device__ float g_G[NN * HD];
__device__ float g_M[NN * HD];
__device__ float g_agg[NN * HD];
__device__ float g_y[NG * HD];

__device__ __forceinline__ float sp_(float x) {
    return fmaxf(x, 0.f) + log1pf(expf(-fabsf(x)));
}
__device__ __forceinline__ float sigm_(float x) {
    return 1.f / (1.f + expf(-x));
}

__global__ void k_zero() {
    int i = blockIdx.x * blockDim.x + threadIdx.x;
    const int n4 = NN * HD / 4;
    if (i < n4) ((float4*)g_agg)[i] = make_float4(0.f, 0.f, 0.f, 0.f);
    if (i < NG * HD / 4) ((float4*)g_y)[i] = make_float4(0.f, 0.f, 0.f, 0.f);
}

__global__ void k_embed(const int* __restrict__ nodes, const float* __restrict__ embed) {
    int i = blockIdx.x * blockDim.x + threadIdx.x;
    if (i >= NN * (HD / 4)) return;
    int node = nodes[i / (HD / 4)];
    ((float4*)g_x)[i] = ((const float4*)embed)[node * (HD / 4) + (i & (HD / 4 - 1))];
}

// ======================================================================
// Tensor-core GEMM: C[M,N] = act_in(A[M,K]) @ W[K,N], bf16 2-way split
// (hi*hi + hi*lo + lo*hi). Block tile 128x64x32, 8 warps (4m x 2n).
// ACT_IN: 0=identity, 1=softplus. EPI: 0=store, 1=sigmoid(Gb)*sp(acc),
// 2=atomicAdd into C[gidx[row]].
// ======================================================================
#define LDA 40  // bf16 elems per row (80 B): conflict-free ldmatrix

__device__ __forceinline__ void split_bf(float x, __nv_bfloat16& h, __nv_bfloat16& l) {
    h = __float2bfloat16(x);
    l = __float2bfloat16(x - __bfloat162float(h));
}

__device__ __forceinline__ void ldm_x4(uint32_t addr, uint32_t r[4]) {
    asm volatile("ldmatrix.sync.aligned.m8n8.x4.shared.b16 {%0,%1,%2,%3},[%4];"
                 : "=r"(r[0]), "=r"(r[1]), "=r"(r[2]), "=r"(r[3]) : "r"(addr));
}

__device__ __forceinline__ void mma16816(float c[4], const uint32_t a[4],
                                         uint32_t b0, uint32_t b1) {
    asm volatile(
        "mma.sync.aligned.m16n8k16.row.col.f32.bf16.bf16.f32 "
        "{%0,%1,%2,%3},{%4,%5,%6,%7},{%8,%9},{%0,%1,%2,%3};"
        : "+f"(c[0]), "+f"(c[1]), "+f"(c[2]), "+f"(c[3])
        : "r"(a[0]), "r"(a[1]), "r"(a[2]), "r"(a[3]), "r"(b0), "r"(b1));
}

template <int ACT_IN, int EPI>
__global__ void __launch_bounds__(256) k_gemm_tc(
    const float* __restrict__ A, const float* __restrict__ W,
    float* __restrict__ C, const float* __restrict__ Gb,
    const int* __restrict__ gidx, int M, int N, int K) {
    __shared__ __nv_bfloat16 Ash[128 * LDA];
    __shared__ __nv_bfloat16 Asl[128 * LDA];
    __shared__ __nv_bfloat16 Bsh[64 * LDA];
    __shared__ __nv_bfloat16 Bsl[64 * LDA];

    const int tid = threadIdx.x;
    const int lane = tid & 31;
    const int warp = tid >> 5;
    const int wm = warp >> 1;
    const int wn = warp & 1;
    const int m0 = blockIdx.y * 128;
    const int n0 = blockIdx.x * 64;

    float acc[2][4][4];
#pragma unroll
    for (int i = 0; i < 2; i++)
#pragma unroll
        for (int j = 0; j < 4; j++)
#pragma unroll
            for (int q = 0; q < 4; q++) acc[i][j][q] = 0.f;

    const uint32_t sAh = (uint32_t)__cvta_generic_to_shared(Ash);
    const uint32_t sAl = (uint32_t)__cvta_generic_to_shared(Asl);
    const uint32_t sBh = (uint32_t)__cvta_generic_to_shared(Bsh);
    const uint32_t sBl = (uint32_t)__cvta_generic_to_shared(Bsl);

    // A ldmatrix addressing: lanes 0-7 rows0-7/k0, 8-15 rows8-15/k0,
    // 16-23 rows0-7/k8, 24-31 rows8-15/k8
    const int a_row = ((lane >> 3) & 1) * 8 + (lane & 7);
    const int a_kof = (lane >> 4) * 8;
    // B addressing ([n][k] layout): lanes 0-7 n0-7/k0, 8-15 n0-7/k8,
    // 16-23 n8-15/k0, 24-31 n8-15/k8
    const int b_row = ((lane >> 4) & 1) * 8 + (lane & 7);
    const int b_kof = ((lane >> 3) & 1) * 8;

    for (int k0 = 0; k0 < K; k0 += 32) {
        // load + split A tile (128x32)
#pragma unroll
        for (int it = 0; it < 4; it++) {
            int lin = tid + it * 256;
            int arow = lin >> 3;
            int kc = (lin & 7) * 4;
            int grow = m0 + arow;
            float4 v = make_float4(0.f, 0.f, 0.f, 0.f);
            if (grow < M) v = *reinterpret_cast<const float4*>(&A[(long)grow * K + k0 + kc]);
            if (ACT_IN == 1) { v.x = sp_(v.x); v.y = sp_(v.y); v.z = sp_(v.z); v.w = sp_(v.w); }
            __nv_bfloat16 h0, h1, h2, h3, l0, l1, l2, l3;
            split_bf(v.x, h0, l0); split_bf(v.y, h1, l1);
            split_bf(v.z, h2, l2); split_bf(v.w, h3, l3);
            int off = arow * LDA + kc;
            Ash[off] = h0; Ash[off + 1] = h1; Ash[off + 2] = h2; Ash[off + 3] = h3;
            Asl[off] = l0; Asl[off + 1] = l1; Asl[off + 2] = l2; Asl[off + 3] = l3;
        }
        // load + split B tile (32x64), stored transposed [n][k]
#pragma unroll
        for (int it = 0; it < 8; it++) {
            int lin = tid + it * 256;
            int bk = lin >> 6;
            int bn = lin & 63;
            float w = W[(long)(k0 + bk) * N + n0 + bn];
            __nv_bfloat16 h, l;
            split_bf(w, h, l);
            Bsh[bn * LDA + bk] = h;
            Bsl[bn * LDA + bk] = l;
        }
        __syncthreads();

#pragma unroll
        for (int ks = 0; ks < 32; ks += 16) {
            uint32_t fah[2][4], fal[2][4], fbh[2][4], fbl[2][4];
#pragma unroll
            for (int mt = 0; mt < 2; mt++) {
                uint32_t off = (uint32_t)((wm * 32 + mt * 16 + a_row) * LDA + ks + a_kof) * 2u;
                ldm_x4(sAh + off, fah[mt]);
                ldm_x4(sAl + off, fal[mt]);
            }
#pragma unroll
            for (int np = 0; np < 2; np++) {
                uint32_t off = (uint32_t)((wn * 32 + np * 16 + b_row) * LDA + ks + b_kof) * 2u;
                ldm_x4(sBh + off, fbh[np]);
                ldm_x4(sBl + off, fbl[np]);
            }
#pragma unroll
            for (int mt = 0; mt < 2; mt++) {
#pragma unroll
                for (int nt = 0; nt < 4; nt++) {
                    uint32_t h0 = fbh[nt >> 1][(nt & 1) * 2];
                    uint32_t h1 = fbh[nt >> 1][(nt & 1) * 2 + 1];
                    uint32_t l0 = fbl[nt >> 1][(nt & 1) * 2];
                    uint32_t l1 = fbl[nt >> 1][(nt & 1) * 2 + 1];
                    mma16816(acc[mt][nt], fah[mt], h0, h1);
                    mma16816(acc[mt][nt], fah[mt], l0, l1);
                    mma16816(acc[mt][nt], fal[mt], h0, h1);
                }
            }
        }
        __syncthreads();
    }

    // epilogue
#pragma unroll
    for (int mt = 0; mt < 2; mt++) {
#pragma unroll
        for (int nt = 0; nt < 4; nt++) {
            int rbase = m0 + wm * 32 + mt * 16 + (lane >> 2);
            int col = n0 + wn * 32 + nt * 8 + (lane & 3) * 2;
            float* c = acc[mt][nt];
#pragma unroll
            for (int half = 0; half < 2; half++) {
                int row = rbase + half * 8;
                if (row >= M) continue;
                float v0 = c[half * 2], v1 = c[half * 2 + 1];
                long base = (long)row * N + col;
                if (EPI == 0) {
                    *reinterpret_cast<float2*>(&C[base]) = make_float2(v0, v1);
                } else if (EPI == 1) {
                    float2 g2 = *reinterpret_cast<const float2*>(&Gb[base]);
                    *reinterpret_cast<float2*>(&C[base]) =
                        make_float2(sigm_(g2.x) * sp_(v0), sigm_(g2.y) * sp_(v1));
                } else {
                    int seg = gidx[row];
                    atomicAdd(&C[(long)seg * N + col], v0);
                    atomicAdd(&C[(long)seg * N + col + 1], v1);
                }
            }
        }
    }
}

// ---- edge scatter with float4 vector atomics ----
__global__ void k_scatter(const int* __restrict__ src, const int* __restrict__ tgt) {
    long i = (long)blockIdx.x * blockDim.x + threadIdx.x;
    if (i >= (long)NE * (HD / 4)) return;
    int e = (int)(i >> 5);
    int c = (int)(i & 31);
    int s = src[e], t = tgt[e];
    float4 v = ((const float4*)g_M)[(long)s * 32 + c];
    atomicAdd(reinterpret_cast<float4*>(&g_agg[(long)t * HD + c * 4]), v);
}

__global__ void k_update() {
    int i = blockIdx.x * blockDim.x + threadIdx.x;
    if (i >= NN * (HD / 4)) return;
    float4 a = ((float4*)g_agg)[i];
    float4 x = ((float4*)g_x)[i];
    x.x += sp_(a.x);
    x.y += sp_(a.y);
    x.z += sp_(a.z);
    x.w += sp_(a.w);
    ((float4*)g_x)[i] = x;
    ((float4*)g_agg)[i] = make_float4(0.f, 0.f, 0.f, 0.f);
}

__global__ void k_mlp(const float* __restrict__ counts,
                      const float* __restrict__ Wfc1, const float* __restrict__ bfc1,
                      const float* __restrict__ Wfc2, const float* __restrict__ bfc2,
                      const float* __restrict__ Wr, const float* __restrict__ br,
                      float* __restrict__ out) {
    __shared__ float s0[HD];
    __shared__ float s1[HD];
    __shared__ float red[HD];
    int g = blockIdx.x, t = threadIdx.x;

    float yv = g_y[g * HD + t] / counts[g];
    s0[t] = sp_(yv);
    __syncthreads();

    float acc = bfc1[t];
#pragma unroll 8
    for (int k = 0; k < HD; k++) acc += s0[k] * Wfc1[k * HD + t];
    s1[t] = sp_(acc);
    __syncthreads();

    acc = bfc2[t];
#pragma unroll 8
    for (int k = 0; k < HD; k++) acc += s1[k] * Wfc2[k * HD + t];
    float h2 = sp_(acc);

    red[t] = h2 * Wr[t];
    __syncthreads();
    for (int s = HD / 2; s > 0; s >>= 1) {
        if (t < s) red[t] += red[t + s];
        __syncthreads();
    }
    if (t == 0) out[g] = red[0] + br[0];
}

extern "C" void kernel_launch(void* const* d_in, const int* in_sizes, int n_in,
                              void* d_out, int out_size) {
    const int* nodes = (const int*)d_in[0];
    const int* esrc = (const int*)d_in[1];
    const int* etgt = (const int*)d_in[2];
    const int* gidx = (const int*)d_in[3];
    const float* counts = (const float*)d_in[4];
    const float* embed = (const float*)d_in[5];
    const float* Wg = (const float*)d_in[6];
    const float* We1 = (const float*)d_in[7];
    const float* We2 = (const float*)d_in[8];
    const float* Wp = (const float*)d_in[9];
    const float* Wfc1 = (const float*)d_in[10];
    const float* bfc1 = (const float*)d_in[11];
    const float* Wfc2 = (const float*)d_in[12];
    const float* bfc2 = (const float*)d_in[13];
    const float* Wr = (const float*)d_in[14];
    const float* br = (const float*)d_in[15];
    float* out = (float*)d_out;

    float *px, *pA, *pG, *pM, *py;
    cudaGetSymbolAddress((void**)&px, g_x);
    cudaGetSymbolAddress((void**)&pA, g_A);
    cudaGetSymbolAddress((void**)&pG, g_G);
    cudaGetSymbolAddress((void**)&pM, g_M);
    cudaGetSymbolAddress((void**)&py, g_y);

    const int blocksM = (NN + 127) / 128;

    {
        int n = NN * HD / 4;
        k_zero<<<(n + 255) / 256, 256>>>();
    }
    {
        int n = NN * (HD / 4);
        k_embed<<<(n + 255) / 256, 256>>>(nodes, embed);
    }
    for (int i = 0; i < NCONV; i++) {
        k_gemm_tc<0, 0><<<dim3(EF / 64, blocksM), 256>>>(
            px, We1 + (long)i * HD * EF, pA, nullptr, nullptr, NN, EF, HD);
        k_gemm_tc<0, 0><<<dim3(HD / 64, blocksM), 256>>>(
            px, Wg + (long)i * HD * HD, pG, nullptr, nullptr, NN, HD, HD);
        k_gemm_tc<1, 1><<<dim3(HD / 64, blocksM), 256>>>(
            pA, We2 + (long)i * EF * HD, pM, pG, nullptr, NN, HD, EF);
        {
            long n = (long)NE * (HD / 4);
            k_scatter<<<(int)((n + 255) / 256), 256>>>(esrc, etgt);
        }
        {
            int n = NN * (HD / 4);
            k_update<<<(n + 255) / 256, 256>>>();
        }
    }
    k_gemm_tc<0, 2><<<dim3(HD / 64, blocksM), 256>>>(
        px, Wp, py, nullptr, gidx, NN, HD, HD);
    k_mlp<<<NG, HD>>>(counts, Wfc1, bfc1, Wfc2, bfc2, Wr, br, out);
}

// round 4
// speedup vs baseline: 2.0992x; 1.5093x over previous
#include <cuda_runtime.h>
#include <cuda_bf16.h>
#include <cstdint>
#include <math.h>

#define NN 100000
#define NE 600000
#define NG 512
#define HD 128
#define EF 256
#define NCONV 3

// ---- scratch (device globals) ----
__device__ float g_x[NN * HD];                 // fp32 master node features
__device__ __nv_bfloat16 g_xh[NN * HD];        // split copies for MMA
__device__ __nv_bfloat16 g_xl[NN * HD];
__device__ __nv_bfloat16 g_Ah[NN * EF];        // sp(x@We1) split
__device__ __nv_bfloat16 g_Al[NN * EF];
__device__ float g_sG[NN * HD];                // sigmoid(x@Wg)
__device__ float g_M[NN * HD];
__device__ float g_agg[NN * HD];
__device__ float g_y[NG * HD];
// transposed split weights [N][K]
#define WE1T(c) ((c) * 32768)
#define WGT(c) (98304 + (c) * 16384)
#define WE2T(c) (147456 + (c) * 32768)
#define WPT 245760
__device__ __nv_bfloat16 g_Wth[262144];
__device__ __nv_bfloat16 g_Wtl[262144];

__device__ __forceinline__ float sp_(float x) {
    return fmaxf(x, 0.f) + log1pf(expf(-fabsf(x)));
}
__device__ __forceinline__ float sigm_(float x) {
    return 1.f / (1.f + expf(-x));
}
__device__ __forceinline__ void split_bf(float x, __nv_bfloat16& h, __nv_bfloat16& l) {
    h = __float2bfloat16(x);
    l = __float2bfloat16(x - __bfloat162float(h));
}

// ---- weight transpose + split (all weights, one launch) ----
__global__ void k_wsplit_all(const float* __restrict__ Wg, const float* __restrict__ We1,
                             const float* __restrict__ We2, const float* __restrict__ Wp) {
    int i = blockIdx.x * blockDim.x + threadIdx.x;
    if (i >= 262144) return;
    float w;
    if (i < 98304) {                       // We1_t[c][n=256][k=128]
        int c = i / 32768, j = i % 32768;
        int n = j / HD, k = j % HD;
        w = We1[c * 32768 + k * EF + n];
    } else if (i < 147456) {               // Wg_t[c][n=128][k=128]
        int i2 = i - 98304;
        int c = i2 / 16384, j = i2 % 16384;
        int n = j / HD, k = j % HD;
        w = Wg[c * 16384 + k * HD + n];
    } else if (i < 245760) {               // We2_t[c][n=128][k=256]
        int i3 = i - 147456;
        int c = i3 / 32768, j = i3 % 32768;
        int n = j >> 8, k = j & 255;
        w = We2[c * 32768 + k * HD + n];
    } else {                               // Wp_t[n=128][k=128]
        int j = i - 245760;
        int n = j / HD, k = j % HD;
        w = Wp[k * HD + n];
    }
    __nv_bfloat16 h, l;
    split_bf(w, h, l);
    g_Wth[i] = h;
    g_Wtl[i] = l;
}

__global__ void k_zero() {
    int i = blockIdx.x * blockDim.x + threadIdx.x;
    const int n4 = NN * HD / 4;
    if (i < n4) ((float4*)g_agg)[i] = make_float4(0.f, 0.f, 0.f, 0.f);
    if (i < NG * HD / 4) ((float4*)g_y)[i] = make_float4(0.f, 0.f, 0.f, 0.f);
}

__device__ __forceinline__ void store_split4(int i4, float4 v) {
    __nv_bfloat16 h0, h1, h2, h3, l0, l1, l2, l3;
    split_bf(v.x, h0, l0); split_bf(v.y, h1, l1);
    split_bf(v.z, h2, l2); split_bf(v.w, h3, l3);
    ((__nv_bfloat162*)g_xh)[i4 * 2] = __nv_bfloat162(h0, h1);
    ((__nv_bfloat162*)g_xh)[i4 * 2 + 1] = __nv_bfloat162(h2, h3);
    ((__nv_bfloat162*)g_xl)[i4 * 2] = __nv_bfloat162(l0, l1);
    ((__nv_bfloat162*)g_xl)[i4 * 2 + 1] = __nv_bfloat162(l2, l3);
}

__global__ void k_embed(const int* __restrict__ nodes, const float* __restrict__ embed) {
    int i = blockIdx.x * blockDim.x + threadIdx.x;
    if (i >= NN * (HD / 4)) return;
    int node = nodes[i >> 5];
    float4 v = ((const float4*)embed)[node * 32 + (i & 31)];
    ((float4*)g_x)[i] = v;
    store_split4(i, v);
}

// ======================================================================
// bf16 split-3 tensor-core GEMM, resident-bf16 operands, cp.async 2-stage.
// A: hi/lo bf16 [M,K] row-major.  B: hi/lo bf16 [N,K] (pre-transposed).
// Block 128x64x32, 8 warps (4m x 2n), warp tile 32x32.
// EPI: 0 -> C = sigmoid(acc)            (gate)
//      1 -> Ch/Cl = split(softplus(acc)) (edge layer 1)
//      2 -> C = Gb * softplus(acc)       (message; Gb pre-sigmoided)
//      3 -> atomicAdd C[gidx[row]]       (pooling)
// ======================================================================
#define LDA 40

__device__ __forceinline__ void cp16(uint32_t dst, const void* src, bool pred) {
    int sz = pred ? 16 : 0;
    asm volatile("cp.async.cg.shared.global [%0], [%1], 16, %2;"
                 :: "r"(dst), "l"(src), "r"(sz));
}
__device__ __forceinline__ void cp_commit() {
    asm volatile("cp.async.commit_group;");
}
template <int N_>
__device__ __forceinline__ void cp_wait() {
    asm volatile("cp.async.wait_group %0;" :: "n"(N_));
}

__device__ __forceinline__ void ldm_x4(uint32_t addr, uint32_t r[4]) {
    asm volatile("ldmatrix.sync.aligned.m8n8.x4.shared.b16 {%0,%1,%2,%3},[%4];"
                 : "=r"(r[0]), "=r"(r[1]), "=r"(r[2]), "=r"(r[3]) : "r"(addr));
}
__device__ __forceinline__ void mma16816(float c[4], const uint32_t a[4],
                                         uint32_t b0, uint32_t b1) {
    asm volatile(
        "mma.sync.aligned.m16n8k16.row.col.f32.bf16.bf16.f32 "
        "{%0,%1,%2,%3},{%4,%5,%6,%7},{%8,%9},{%0,%1,%2,%3};"
        : "+f"(c[0]), "+f"(c[1]), "+f"(c[2]), "+f"(c[3])
        : "r"(a[0]), "r"(a[1]), "r"(a[2]), "r"(a[3]), "r"(b0), "r"(b1));
}

template <int EPI>
__global__ void __launch_bounds__(256) k_gemm_bf(
    const __nv_bfloat16* __restrict__ Ah, const __nv_bfloat16* __restrict__ Al,
    const __nv_bfloat16* __restrict__ Bh, const __nv_bfloat16* __restrict__ Bl,
    float* __restrict__ C, const float* __restrict__ Gb, const int* __restrict__ gidx,
    __nv_bfloat16* __restrict__ Ch, __nv_bfloat16* __restrict__ Cl,
    int M, int N, int K) {
    __shared__ __nv_bfloat16 sA[2][2][128 * LDA];
    __shared__ __nv_bfloat16 sB[2][2][64 * LDA];

    const int tid = threadIdx.x;
    const int lane = tid & 31;
    const int warp = tid >> 5;
    const int wm = warp >> 1;
    const int wn = warp & 1;
    const int m0 = blockIdx.y * 128;
    const int n0 = blockIdx.x * 64;

    float acc[2][4][4];
#pragma unroll
    for (int i = 0; i < 2; i++)
#pragma unroll
        for (int j = 0; j < 4; j++)
#pragma unroll
            for (int q = 0; q < 4; q++) acc[i][j][q] = 0.f;

    uint32_t aB[2][2], bB[2][2];
#pragma unroll
    for (int st = 0; st < 2; st++)
#pragma unroll
        for (int hl = 0; hl < 2; hl++) {
            aB[st][hl] = (uint32_t)__cvta_generic_to_shared(&sA[st][hl][0]);
            bB[st][hl] = (uint32_t)__cvta_generic_to_shared(&sB[st][hl][0]);
        }

    // per-thread load coords
    const int a_r0 = tid >> 2;            // +256>>2 for second half
    const int a_kc = (tid & 3) * 8;
    const int b_r = tid >> 2;             // 0..63
    const int b_kc = (tid & 3) * 8;

    // ldmatrix lane addressing (proven in R3)
    const int a_row = ((lane >> 3) & 1) * 8 + (lane & 7);
    const int a_kof = (lane >> 4) * 8;
    const int b_row = ((lane >> 4) & 1) * 8 + (lane & 7);
    const int b_kof = ((lane >> 3) & 1) * 8;

    const int T = K / 32;

    auto load_stage = [&](int st, int k0) {
#pragma unroll
        for (int it = 0; it < 2; it++) {
            int row = a_r0 + it * 64;
            bool p = (m0 + row) < M;
            long g = (long)(m0 + row) * K + k0 + a_kc;
            if (!p) g = 0;
            uint32_t off = (uint32_t)(row * LDA + a_kc) * 2u;
            cp16(aB[st][0] + off, Ah + g, p);
            cp16(aB[st][1] + off, Al + g, p);
        }
        {
            long g = (long)(n0 + b_r) * K + k0 + b_kc;
            uint32_t off = (uint32_t)(b_r * LDA + b_kc) * 2u;
            cp16(bB[st][0] + off, Bh + g, true);
            cp16(bB[st][1] + off, Bl + g, true);
        }
    };

    load_stage(0, 0);
    cp_commit();

    for (int kt = 0; kt < T; kt++) {
        if (kt + 1 < T) {
            load_stage((kt + 1) & 1, (kt + 1) * 32);
            cp_commit();
            cp_wait<1>();
        } else {
            cp_wait<0>();
        }
        __syncthreads();

        int st = kt & 1;
#pragma unroll
        for (int ks = 0; ks < 32; ks += 16) {
            uint32_t fah[2][4], fal[2][4], fbh[2][4], fbl[2][4];
#pragma unroll
            for (int mt = 0; mt < 2; mt++) {
                uint32_t off = (uint32_t)((wm * 32 + mt * 16 + a_row) * LDA + ks + a_kof) * 2u;
                ldm_x4(aB[st][0] + off, fah[mt]);
                ldm_x4(aB[st][1] + off, fal[mt]);
            }
#pragma unroll
            for (int np = 0; np < 2; np++) {
                uint32_t off = (uint32_t)((wn * 32 + np * 16 + b_row) * LDA + ks + b_kof) * 2u;
                ldm_x4(bB[st][0] + off, fbh[np]);
                ldm_x4(bB[st][1] + off, fbl[np]);
            }
#pragma unroll
            for (int mt = 0; mt < 2; mt++) {
#pragma unroll
                for (int nt = 0; nt < 4; nt++) {
                    uint32_t h0 = fbh[nt >> 1][(nt & 1) * 2];
                    uint32_t h1 = fbh[nt >> 1][(nt & 1) * 2 + 1];
                    uint32_t l0 = fbl[nt >> 1][(nt & 1) * 2];
                    uint32_t l1 = fbl[nt >> 1][(nt & 1) * 2 + 1];
                    mma16816(acc[mt][nt], fah[mt], h0, h1);
                    mma16816(acc[mt][nt], fah[mt], l0, l1);
                    mma16816(acc[mt][nt], fal[mt], h0, h1);
                }
            }
        }
        __syncthreads();
    }

    // epilogue
#pragma unroll
    for (int mt = 0; mt < 2; mt++) {
#pragma unroll
        for (int nt = 0; nt < 4; nt++) {
            int rbase = m0 + wm * 32 + mt * 16 + (lane >> 2);
            int col = n0 + wn * 32 + nt * 8 + (lane & 3) * 2;
            float* c = acc[mt][nt];
#pragma unroll
            for (int half = 0; half < 2; half++) {
                int row = rbase + half * 8;
                if (row >= M) continue;
                float v0 = c[half * 2], v1 = c[half * 2 + 1];
                long base = (long)row * N + col;
                if (EPI == 0) {
                    *reinterpret_cast<float2*>(&C[base]) = make_float2(sigm_(v0), sigm_(v1));
                } else if (EPI == 1) {
                    __nv_bfloat16 h0, h1, l0, l1;
                    split_bf(sp_(v0), h0, l0);
                    split_bf(sp_(v1), h1, l1);
                    *reinterpret_cast<__nv_bfloat162*>(&Ch[base]) = __nv_bfloat162(h0, h1);
                    *reinterpret_cast<__nv_bfloat162*>(&Cl[base]) = __nv_bfloat162(l0, l1);
                } else if (EPI == 2) {
                    float2 g2 = *reinterpret_cast<const float2*>(&Gb[base]);
                    *reinterpret_cast<float2*>(&C[base]) =
                        make_float2(g2.x * sp_(v0), g2.y * sp_(v1));
                } else {
                    int seg = gidx[row];
                    atomicAdd(reinterpret_cast<float2*>(&C[(long)seg * N + col]),
                              make_float2(v0, v1));
                }
            }
        }
    }
}

// ---- edge scatter with float4 vector atomics ----
__global__ void k_scatter(const int* __restrict__ src, const int* __restrict__ tgt) {
    long i = (long)blockIdx.x * blockDim.x + threadIdx.x;
    if (i >= (long)NE * (HD / 4)) return;
    int e = (int)(i >> 5);
    int c = (int)(i & 31);
    int s = src[e], t = tgt[e];
    float4 v = ((const float4*)g_M)[(long)s * 32 + c];
    atomicAdd(reinterpret_cast<float4*>(&g_agg[(long)t * HD + c * 4]), v);
}

// ---- node update: x += sp(agg); refresh split copies; zero agg ----
__global__ void k_update() {
    int i = blockIdx.x * blockDim.x + threadIdx.x;
    if (i >= NN * (HD / 4)) return;
    float4 a = ((float4*)g_agg)[i];
    float4 x = ((float4*)g_x)[i];
    x.x += sp_(a.x);
    x.y += sp_(a.y);
    x.z += sp_(a.z);
    x.w += sp_(a.w);
    ((float4*)g_x)[i] = x;
    store_split4(i, x);
    ((float4*)g_agg)[i] = make_float4(0.f, 0.f, 0.f, 0.f);
}

// ---- per-graph MLP head ----
__global__ void k_mlp(const float* __restrict__ counts,
                      const float* __restrict__ Wfc1, const float* __restrict__ bfc1,
                      const float* __restrict__ Wfc2, const float* __restrict__ bfc2,
                      const float* __restrict__ Wr, const float* __restrict__ br,
                      float* __restrict__ out) {
    __shared__ float s0[HD];
    __shared__ float s1[HD];
    __shared__ float red[HD];
    int g = blockIdx.x, t = threadIdx.x;

    float yv = g_y[g * HD + t] / counts[g];
    s0[t] = sp_(yv);
    __syncthreads();

    float acc = bfc1[t];
#pragma unroll 8
    for (int k = 0; k < HD; k++) acc += s0[k] * Wfc1[k * HD + t];
    s1[t] = sp_(acc);
    __syncthreads();

    acc = bfc2[t];
#pragma unroll 8
    for (int k = 0; k < HD; k++) acc += s1[k] * Wfc2[k * HD + t];
    float h2 = sp_(acc);

    red[t] = h2 * Wr[t];
    __syncthreads();
    for (int s = HD / 2; s > 0; s >>= 1) {
        if (t < s) red[t] += red[t + s];
        __syncthreads();
    }
    if (t == 0) out[g] = red[0] + br[0];
}

extern "C" void kernel_launch(void* const* d_in, const int* in_sizes, int n_in,
                              void* d_out, int out_size) {
    const int* nodes = (const int*)d_in[0];
    const int* esrc = (const int*)d_in[1];
    const int* etgt = (const int*)d_in[2];
    const int* gidx = (const int*)d_in[3];
    const float* counts = (const float*)d_in[4];
    const float* embed = (const float*)d_in[5];
    const float* Wg = (const float*)d_in[6];
    const float* We1 = (const float*)d_in[7];
    const float* We2 = (const float*)d_in[8];
    const float* Wp = (const float*)d_in[9];
    const float* Wfc1 = (const float*)d_in[10];
    const float* bfc1 = (const float*)d_in[11];
    const float* Wfc2 = (const float*)d_in[12];
    const float* bfc2 = (const float*)d_in[13];
    const float* Wr = (const float*)d_in[14];
    const float* br = (const float*)d_in[15];
    float* out = (float*)d_out;

    __nv_bfloat16 *pxh, *pxl, *pAh, *pAl, *pWth, *pWtl;
    float *psG, *pM, *py;
    cudaGetSymbolAddress((void**)&pxh, g_xh);
    cudaGetSymbolAddress((void**)&pxl, g_xl);
    cudaGetSymbolAddress((void**)&pAh, g_Ah);
    cudaGetSymbolAddress((void**)&pAl, g_Al);
    cudaGetSymbolAddress((void**)&pWth, g_Wth);
    cudaGetSymbolAddress((void**)&pWtl, g_Wtl);
    cudaGetSymbolAddress((void**)&psG, g_sG);
    cudaGetSymbolAddress((void**)&pM, g_M);
    cudaGetSymbolAddress((void**)&py, g_y);

    const int blocksM = (NN + 127) / 128;

    k_wsplit_all<<<(262144 + 255) / 256, 256>>>(Wg, We1, We2, Wp);
    {
        int n = NN * HD / 4;
        k_zero<<<(n + 255) / 256, 256>>>();
    }
    {
        int n = NN * (HD / 4);
        k_embed<<<(n + 255) / 256, 256>>>(nodes, embed);
    }
    for (int i = 0; i < NCONV; i++) {
        // sp(x @ We1) -> split bf16 g_A
        k_gemm_bf<1><<<dim3(EF / 64, blocksM), 256>>>(
            pxh, pxl, pWth + WE1T(i), pWtl + WE1T(i),
            nullptr, nullptr, nullptr, pAh, pAl, NN, EF, HD);
        // sigmoid(x @ Wg) -> g_sG
        k_gemm_bf<0><<<dim3(HD / 64, blocksM), 256>>>(
            pxh, pxl, pWth + WGT(i), pWtl + WGT(i),
            psG, nullptr, nullptr, nullptr, nullptr, NN, HD, HD);
        // M = sG * sp(A @ We2)
        k_gemm_bf<2><<<dim3(HD / 64, blocksM), 256>>>(
            pAh, pAl, pWth + WE2T(i), pWtl + WE2T(i),
            pM, psG, nullptr, nullptr, nullptr, NN, HD, EF);
        {
            long n = (long)NE * (HD / 4);
            k_scatter<<<(int)((n + 255) / 256), 256>>>(esrc, etgt);
        }
        {
            int n = NN * (HD / 4);
            k_update<<<(n + 255) / 256, 256>>>();
        }
    }
    // pooling with fused segment atomics
    k_gemm_bf<3><<<dim3(HD / 64, blocksM), 256>>>(
        pxh, pxl, pWth + WPT, pWtl + WPT,
        py, nullptr, gidx, nullptr, nullptr, NN, HD, HD);
    k_mlp<<<NG, HD>>>(counts, Wfc1, bfc1, Wfc2, bfc2, Wr, br, out);
}

// round 5
// speedup vs baseline: 2.2177x; 1.0564x over previous
#include <cuda_runtime.h>
#include <cuda_bf16.h>
#include <cstdint>
#include <math.h>

#define NN 100000
#define NE 600000
#define NG 512
#define HD 128
#define EF 256
#define NCONV 3

// ---- scratch (device globals) ----
__device__ float g_x[NN * HD];
__device__ __nv_bfloat16 g_xh[NN * HD];
__device__ __nv_bfloat16 g_xl[NN * HD];
__device__ __nv_bfloat16 g_Ah[NN * EF];
__device__ __nv_bfloat16 g_Al[NN * EF];
__device__ float g_sG[NN * HD];
__device__ float g_M[NN * HD];
__device__ float g_agg[NN * HD];
__device__ float g_y[NG * HD];
#define WE1T(c) ((c) * 32768)
#define WGT(c) (98304 + (c) * 16384)
#define WE2T(c) (147456 + (c) * 32768)
#define WPT 245760
__device__ __nv_bfloat16 g_Wth[262144];
__device__ __nv_bfloat16 g_Wtl[262144];

__device__ __forceinline__ float sp_(float x) {
    return fmaxf(x, 0.f) + log1pf(expf(-fabsf(x)));
}
__device__ __forceinline__ float sigm_(float x) {
    return 1.f / (1.f + expf(-x));
}
__device__ __forceinline__ void split_bf(float x, __nv_bfloat16& h, __nv_bfloat16& l) {
    h = __float2bfloat16(x);
    l = __float2bfloat16(x - __bfloat162float(h));
}

__global__ void k_wsplit_all(const float* __restrict__ Wg, const float* __restrict__ We1,
                             const float* __restrict__ We2, const float* __restrict__ Wp) {
    int i = blockIdx.x * blockDim.x + threadIdx.x;
    if (i >= 262144) return;
    float w;
    if (i < 98304) {
        int c = i / 32768, j = i % 32768;
        int n = j / HD, k = j % HD;
        w = We1[c * 32768 + k * EF + n];
    } else if (i < 147456) {
        int i2 = i - 98304;
        int c = i2 / 16384, j = i2 % 16384;
        int n = j / HD, k = j % HD;
        w = Wg[c * 16384 + k * HD + n];
    } else if (i < 245760) {
        int i3 = i - 147456;
        int c = i3 / 32768, j = i3 % 32768;
        int n = j >> 8, k = j & 255;
        w = We2[c * 32768 + k * HD + n];
    } else {
        int j = i - 245760;
        int n = j / HD, k = j % HD;
        w = Wp[k * HD + n];
    }
    __nv_bfloat16 h, l;
    split_bf(w, h, l);
    g_Wth[i] = h;
    g_Wtl[i] = l;
}

__global__ void k_zero() {
    int i = blockIdx.x * blockDim.x + threadIdx.x;
    const int n4 = NN * HD / 4;
    if (i < n4) ((float4*)g_agg)[i] = make_float4(0.f, 0.f, 0.f, 0.f);
    if (i < NG * HD / 4) ((float4*)g_y)[i] = make_float4(0.f, 0.f, 0.f, 0.f);
}

__device__ __forceinline__ void store_split4(int i4, float4 v) {
    __nv_bfloat16 h0, h1, h2, h3, l0, l1, l2, l3;
    split_bf(v.x, h0, l0); split_bf(v.y, h1, l1);
    split_bf(v.z, h2, l2); split_bf(v.w, h3, l3);
    ((__nv_bfloat162*)g_xh)[i4 * 2] = __nv_bfloat162(h0, h1);
    ((__nv_bfloat162*)g_xh)[i4 * 2 + 1] = __nv_bfloat162(h2, h3);
    ((__nv_bfloat162*)g_xl)[i4 * 2] = __nv_bfloat162(l0, l1);
    ((__nv_bfloat162*)g_xl)[i4 * 2 + 1] = __nv_bfloat162(l2, l3);
}

__global__ void k_embed(const int* __restrict__ nodes, const float* __restrict__ embed) {
    int i = blockIdx.x * blockDim.x + threadIdx.x;
    if (i >= NN * (HD / 4)) return;
    int node = nodes[i >> 5];
    float4 v = ((const float4*)embed)[node * 32 + (i & 31)];
    ((float4*)g_x)[i] = v;
    store_split4(i, v);
}

// ======================================================================
// bf16 split-3 MMA GEMM, compile-time N/K, fully unrolled k-loop.
// A: hi/lo bf16 [M,K].  B: hi/lo bf16 [N,K].  Block 128x64x32, 8 warps.
// EPI: 0 sigmoid -> C; 1 split(softplus) -> Ch/Cl; 2 Gb*softplus -> C;
//      3 atomicAdd C[gidx[row]]
// ======================================================================
#define LDA 40

__device__ __forceinline__ void cp16(uint32_t dst, const void* src, bool pred) {
    int sz = pred ? 16 : 0;
    asm volatile("cp.async.cg.shared.global [%0], [%1], 16, %2;"
                 :: "r"(dst), "l"(src), "r"(sz));
}
__device__ __forceinline__ void cp_commit() {
    asm volatile("cp.async.commit_group;");
}
template <int N_>
__device__ __forceinline__ void cp_wait() {
    asm volatile("cp.async.wait_group %0;" :: "n"(N_));
}
__device__ __forceinline__ void ldm_x4(uint32_t addr, uint32_t r[4]) {
    asm volatile("ldmatrix.sync.aligned.m8n8.x4.shared.b16 {%0,%1,%2,%3},[%4];"
                 : "=r"(r[0]), "=r"(r[1]), "=r"(r[2]), "=r"(r[3]) : "r"(addr));
}
__device__ __forceinline__ void mma16816(float c[4], const uint32_t a[4],
                                         uint32_t b0, uint32_t b1) {
    asm volatile(
        "mma.sync.aligned.m16n8k16.row.col.f32.bf16.bf16.f32 "
        "{%0,%1,%2,%3},{%4,%5,%6,%7},{%8,%9},{%0,%1,%2,%3};"
        : "+f"(c[0]), "+f"(c[1]), "+f"(c[2]), "+f"(c[3])
        : "r"(a[0]), "r"(a[1]), "r"(a[2]), "r"(a[3]), "r"(b0), "r"(b1));
}

template <int EPI, int NT_, int KT_>
__global__ void __launch_bounds__(256) k_gemm_bf(
    const __nv_bfloat16* __restrict__ Ah, const __nv_bfloat16* __restrict__ Al,
    const __nv_bfloat16* __restrict__ Bh, const __nv_bfloat16* __restrict__ Bl,
    float* __restrict__ C, const float* __restrict__ Gb, const int* __restrict__ gidx,
    __nv_bfloat16* __restrict__ Ch, __nv_bfloat16* __restrict__ Cl,
    int M) {
    constexpr int N = NT_;
    constexpr int K = KT_;
    constexpr int T = K / 32;

    __shared__ __nv_bfloat16 sA[2][2][128 * LDA];
    __shared__ __nv_bfloat16 sB[2][2][64 * LDA];

    const int tid = threadIdx.x;
    const int lane = tid & 31;
    const int warp = tid >> 5;
    const int wm = warp >> 1;
    const int wn = warp & 1;
    const int m0 = blockIdx.y * 128;
    const int n0 = blockIdx.x * 64;

    float acc[2][4][4];
#pragma unroll
    for (int i = 0; i < 2; i++)
#pragma unroll
        for (int j = 0; j < 4; j++)
#pragma unroll
            for (int q = 0; q < 4; q++) acc[i][j][q] = 0.f;

    uint32_t aB[2][2], bB[2][2];
#pragma unroll
    for (int st = 0; st < 2; st++)
#pragma unroll
        for (int hl = 0; hl < 2; hl++) {
            aB[st][hl] = (uint32_t)__cvta_generic_to_shared(&sA[st][hl][0]);
            bB[st][hl] = (uint32_t)__cvta_generic_to_shared(&sB[st][hl][0]);
        }

    const int a_r0 = tid >> 2;
    const int a_kc = (tid & 3) * 8;
    const int b_r = tid >> 2;
    const int b_kc = (tid & 3) * 8;

    const int a_row = ((lane >> 3) & 1) * 8 + (lane & 7);
    const int a_kof = (lane >> 4) * 8;
    const int b_row = ((lane >> 4) & 1) * 8 + (lane & 7);
    const int b_kof = ((lane >> 3) & 1) * 8;

    // precomputed per-thread constants
    const bool pA0 = (m0 + a_r0) < M;
    const bool pA1 = (m0 + a_r0 + 64) < M;
    const uint32_t aOff0 = (uint32_t)(a_r0 * LDA + a_kc) * 2u;
    const uint32_t aOff1 = (uint32_t)((a_r0 + 64) * LDA + a_kc) * 2u;
    const uint32_t bOff = (uint32_t)(b_r * LDA + b_kc) * 2u;
    const __nv_bfloat16* gAh0 = Ah + (pA0 ? (long)(m0 + a_r0) * K + a_kc : 0);
    const __nv_bfloat16* gAl0 = Al + (pA0 ? (long)(m0 + a_r0) * K + a_kc : 0);
    const __nv_bfloat16* gAh1 = Ah + (pA1 ? (long)(m0 + a_r0 + 64) * K + a_kc : 0);
    const __nv_bfloat16* gAl1 = Al + (pA1 ? (long)(m0 + a_r0 + 64) * K + a_kc : 0);
    const __nv_bfloat16* gBh = Bh + (long)(n0 + b_r) * K + b_kc;
    const __nv_bfloat16* gBl = Bl + (long)(n0 + b_r) * K + b_kc;

#define LOAD_STAGE(st, k0)                                   \
    do {                                                     \
        cp16(aB[st][0] + aOff0, gAh0 + (k0), pA0);           \
        cp16(aB[st][1] + aOff0, gAl0 + (k0), pA0);           \
        cp16(aB[st][0] + aOff1, gAh1 + (k0), pA1);           \
        cp16(aB[st][1] + aOff1, gAl1 + (k0), pA1);           \
        cp16(bB[st][0] + bOff, gBh + (k0), true);            \
        cp16(bB[st][1] + bOff, gBl + (k0), true);            \
        cp_commit();                                         \
    } while (0)

    LOAD_STAGE(0, 0);

#pragma unroll
    for (int kt = 0; kt < T; kt++) {
        if (kt + 1 < T) {
            LOAD_STAGE((kt + 1) & 1, (kt + 1) * 32);
            cp_wait<1>();
        } else {
            cp_wait<0>();
        }
        __syncthreads();

        const int st = kt & 1;
#pragma unroll
        for (int ks = 0; ks < 32; ks += 16) {
            uint32_t fah[2][4], fal[2][4], fbh[2][4], fbl[2][4];
#pragma unroll
            for (int mt = 0; mt < 2; mt++) {
                uint32_t off = (uint32_t)((wm * 32 + mt * 16 + a_row) * LDA + ks + a_kof) * 2u;
                ldm_x4(aB[st][0] + off, fah[mt]);
                ldm_x4(aB[st][1] + off, fal[mt]);
            }
#pragma unroll
            for (int np = 0; np < 2; np++) {
                uint32_t off = (uint32_t)((wn * 32 + np * 16 + b_row) * LDA + ks + b_kof) * 2u;
                ldm_x4(bB[st][0] + off, fbh[np]);
                ldm_x4(bB[st][1] + off, fbl[np]);
            }
            // term-major schedule: no accumulator reused within 8 MMAs
#pragma unroll
            for (int term = 0; term < 3; term++) {
#pragma unroll
                for (int mt = 0; mt < 2; mt++) {
#pragma unroll
                    for (int nt = 0; nt < 4; nt++) {
                        uint32_t b0, b1;
                        const uint32_t* fa;
                        if (term == 0) {
                            fa = fah[mt];
                            b0 = fbh[nt >> 1][(nt & 1) * 2];
                            b1 = fbh[nt >> 1][(nt & 1) * 2 + 1];
                        } else if (term == 1) {
                            fa = fah[mt];
                            b0 = fbl[nt >> 1][(nt & 1) * 2];
                            b1 = fbl[nt >> 1][(nt & 1) * 2 + 1];
                        } else {
                            fa = fal[mt];
                            b0 = fbh[nt >> 1][(nt & 1) * 2];
                            b1 = fbh[nt >> 1][(nt & 1) * 2 + 1];
                        }
                        mma16816(acc[mt][nt], fa, b0, b1);
                    }
                }
            }
        }
        __syncthreads();
    }
#undef LOAD_STAGE

    // epilogue
#pragma unroll
    for (int mt = 0; mt < 2; mt++) {
#pragma unroll
        for (int nt = 0; nt < 4; nt++) {
            int rbase = m0 + wm * 32 + mt * 16 + (lane >> 2);
            int col = n0 + wn * 32 + nt * 8 + (lane & 3) * 2;
            float* c = acc[mt][nt];
#pragma unroll
            for (int half = 0; half < 2; half++) {
                int row = rbase + half * 8;
                if (row >= M) continue;
                float v0 = c[half * 2], v1 = c[half * 2 + 1];
                long base = (long)row * N + col;
                if (EPI == 0) {
                    *reinterpret_cast<float2*>(&C[base]) = make_float2(sigm_(v0), sigm_(v1));
                } else if (EPI == 1) {
                    __nv_bfloat16 h0, h1, l0, l1;
                    split_bf(sp_(v0), h0, l0);
                    split_bf(sp_(v1), h1, l1);
                    *reinterpret_cast<__nv_bfloat162*>(&Ch[base]) = __nv_bfloat162(h0, h1);
                    *reinterpret_cast<__nv_bfloat162*>(&Cl[base]) = __nv_bfloat162(l0, l1);
                } else if (EPI == 2) {
                    float2 g2 = *reinterpret_cast<const float2*>(&Gb[base]);
                    *reinterpret_cast<float2*>(&C[base]) =
                        make_float2(g2.x * sp_(v0), g2.y * sp_(v1));
                } else {
                    int seg = gidx[row];
                    atomicAdd(reinterpret_cast<float2*>(&C[(long)seg * N + col]),
                              make_float2(v0, v1));
                }
            }
        }
    }
}

// ---- edge scatter with float4 vector atomics ----
__global__ void k_scatter(const int* __restrict__ src, const int* __restrict__ tgt) {
    long i = (long)blockIdx.x * blockDim.x + threadIdx.x;
    if (i >= (long)NE * (HD / 4)) return;
    int e = (int)(i >> 5);
    int c = (int)(i & 31);
    int s = src[e], t = tgt[e];
    float4 v = ((const float4*)g_M)[(long)s * 32 + c];
    atomicAdd(reinterpret_cast<float4*>(&g_agg[(long)t * HD + c * 4]), v);
}

__global__ void k_update() {
    int i = blockIdx.x * blockDim.x + threadIdx.x;
    if (i >= NN * (HD / 4)) return;
    float4 a = ((float4*)g_agg)[i];
    float4 x = ((float4*)g_x)[i];
    x.x += sp_(a.x);
    x.y += sp_(a.y);
    x.z += sp_(a.z);
    x.w += sp_(a.w);
    ((float4*)g_x)[i] = x;
    store_split4(i, x);
    ((float4*)g_agg)[i] = make_float4(0.f, 0.f, 0.f, 0.f);
}

__global__ void k_mlp(const float* __restrict__ counts,
                      const float* __restrict__ Wfc1, const float* __restrict__ bfc1,
                      const float* __restrict__ Wfc2, const float* __restrict__ bfc2,
                      const float* __restrict__ Wr, const float* __restrict__ br,
                      float* __restrict__ out) {
    __shared__ float s0[HD];
    __shared__ float s1[HD];
    __shared__ float red[HD];
    int g = blockIdx.x, t = threadIdx.x;

    float yv = g_y[g * HD + t] / counts[g];
    s0[t] = sp_(yv);
    __syncthreads();

    float acc = bfc1[t];
#pragma unroll 8
    for (int k = 0; k < HD; k++) acc += s0[k] * Wfc1[k * HD + t];
    s1[t] = sp_(acc);
    __syncthreads();

    acc = bfc2[t];
#pragma unroll 8
    for (int k = 0; k < HD; k++) acc += s1[k] * Wfc2[k * HD + t];
    float h2 = sp_(acc);

    red[t] = h2 * Wr[t];
    __syncthreads();
    for (int s = HD / 2; s > 0; s >>= 1) {
        if (t < s) red[t] += red[t + s];
        __syncthreads();
    }
    if (t == 0) out[g] = red[0] + br[0];
}

extern "C" void kernel_launch(void* const* d_in, const int* in_sizes, int n_in,
                              void* d_out, int out_size) {
    const int* nodes = (const int*)d_in[0];
    const int* esrc = (const int*)d_in[1];
    const int* etgt = (const int*)d_in[2];
    const int* gidx = (const int*)d_in[3];
    const float* counts = (const float*)d_in[4];
    const float* embed = (const float*)d_in[5];
    const float* Wg = (const float*)d_in[6];
    const float* We1 = (const float*)d_in[7];
    const float* We2 = (const float*)d_in[8];
    const float* Wp = (const float*)d_in[9];
    const float* Wfc1 = (const float*)d_in[10];
    const float* bfc1 = (const float*)d_in[11];
    const float* Wfc2 = (const float*)d_in[12];
    const float* bfc2 = (const float*)d_in[13];
    const float* Wr = (const float*)d_in[14];
    const float* br = (const float*)d_in[15];
    float* out = (float*)d_out;

    __nv_bfloat16 *pxh, *pxl, *pAh, *pAl, *pWth, *pWtl;
    float *psG, *pM, *py;
    cudaGetSymbolAddress((void**)&pxh, g_xh);
    cudaGetSymbolAddress((void**)&pxl, g_xl);
    cudaGetSymbolAddress((void**)&pAh, g_Ah);
    cudaGetSymbolAddress((void**)&pAl, g_Al);
    cudaGetSymbolAddress((void**)&pWth, g_Wth);
    cudaGetSymbolAddress((void**)&pWtl, g_Wtl);
    cudaGetSymbolAddress((void**)&psG, g_sG);
    cudaGetSymbolAddress((void**)&pM, g_M);
    cudaGetSymbolAddress((void**)&py, g_y);

    const int blocksM = (NN + 127) / 128;

    k_wsplit_all<<<(262144 + 255) / 256, 256>>>(Wg, We1, We2, Wp);
    {
        int n = NN * HD / 4;
        k_zero<<<(n + 255) / 256, 256>>>();
    }
    {
        int n = NN * (HD / 4);
        k_embed<<<(n + 255) / 256, 256>>>(nodes, embed);
    }
    for (int i = 0; i < NCONV; i++) {
        k_gemm_bf<1, EF, HD><<<dim3(EF / 64, blocksM), 256>>>(
            pxh, pxl, pWth + WE1T(i), pWtl + WE1T(i),
            nullptr, nullptr, nullptr, pAh, pAl, NN);
        k_gemm_bf<0, HD, HD><<<dim3(HD / 64, blocksM), 256>>>(
            pxh, pxl, pWth + WGT(i), pWtl + WGT(i),
            psG, nullptr, nullptr, nullptr, nullptr, NN);
        k_gemm_bf<2, HD, EF><<<dim3(HD / 64, blocksM), 256>>>(
            pAh, pAl, pWth + WE2T(i), pWtl + WE2T(i),
            pM, psG, nullptr, nullptr, nullptr, NN);
        {
            long n = (long)NE * (HD / 4);
            k_scatter<<<(int)((n + 255) / 256), 256>>>(esrc, etgt);
        }
        {
            int n = NN * (HD / 4);
            k_update<<<(n + 255) / 256, 256>>>();
        }
    }
    k_gemm_bf<3, HD, HD><<<dim3(HD / 64, blocksM), 256>>>(
        pxh, pxl, pWth + WPT, pWtl + WPT,
        py, nullptr, gidx, nullptr, nullptr, NN);
    k_mlp<<<NG, HD>>>(counts, Wfc1, bfc1, Wfc2, bfc2, Wr, br, out);
}